// round 14
// baseline (speedup 1.0000x reference)
#include <cuda_runtime.h>

#define NN 100000
#define NE 800000
#define IC 96
#define OC 64
#define GN 128            // nodes per GEMM block
#define CHUNK 1024        // scan chunk
#define NB ((NN + CHUNK - 1) / CHUNK)   // 98
static_assert(NB <= 128, "lookback scan assumes <=128 chunks");

// ---- scratch (static device globals; no allocation allowed) ----
// Referenced only from device code; never passed as kernel arguments.
__device__ int   g_is64;          // 1 if edge_index is int64, else int32
__device__ float g_dinv[NN];
__device__ int   g_cnt[NN];
__device__ int   g_rowstart[NN];
__device__ int   g_cursor[NN];
__device__ int   g_pub[128];      // lookback: chunk aggregate + 1 (0 = not ready)
__device__ __align__(16) int2  g_sw[NE];       // CSR-by-dest: (src, weight-bits)
__device__ __align__(16) float g_A[NN * OC];   // h = x W^T, hop-1 source
__device__ __align__(16) float g_B[NN * OC];   // hop-1 result / hop-2 source

// ---------------------------------------------------------------- f32x2 helpers
__device__ __forceinline__ void fma2(unsigned long long& d,
                                     unsigned long long a, unsigned long long b) {
    asm("fma.rn.f32x2 %0, %1, %2, %0;" : "+l"(d) : "l"(a), "l"(b));
}
__device__ __forceinline__ unsigned long long pack2(float x) {
    unsigned long long r;
    asm("mov.b64 %0, {%1, %1};" : "=l"(r) : "f"(x));
    return r;
}

// ---------------------------------------------------------------- init: zero state + dtype detect
__global__ void k_init(const int* __restrict__ ei32) {
    int i = blockIdx.x * blockDim.x + threadIdx.x;
    if (i < NN) g_cnt[i] = 0;
    if (i < 128) g_pub[i] = 0;
    if (i == 0) {
        int nz = 0;
        #pragma unroll 8
        for (int k = 0; k < 64; k++) nz |= ei32[2 * k + 1];
        g_is64 = (nz == 0) ? 1 : 0;   // odd int32 words all zero => int64 data
    }
}

// ---------------------------------------------------------------- count in-degree (c only)
__global__ void k_count(const int* __restrict__ ei32) {
    int e = blockIdx.x * blockDim.x + threadIdx.x;
    if (e < NE) {
        int c = g_is64 ? ei32[2 * (NE + e)] : ei32[NE + e];
        if ((unsigned)c < NN) atomicAdd(&g_cnt[c], 1);
    }
}

// ---------------------------------------------------------------- single-pass scan (decoupled lookback)
__global__ void __launch_bounds__(256) k_scan() {
    __shared__ int s[256];
    __shared__ int s2[256];
    int t = threadIdx.x, b = blockIdx.x;
    int base = b * CHUNK + t * 4;

    int v0 = (base + 0 < NN) ? g_cnt[base + 0] : 0;
    int v1 = (base + 1 < NN) ? g_cnt[base + 1] : 0;
    int v2 = (base + 2 < NN) ? g_cnt[base + 2] : 0;
    int v3 = (base + 3 < NN) ? g_cnt[base + 3] : 0;
    // dinv while cnt is hot (deg includes +1 self loop)
    if (base + 0 < NN) g_dinv[base + 0] = rsqrtf((float)v0 + 1.0f);
    if (base + 1 < NN) g_dinv[base + 1] = rsqrtf((float)v1 + 1.0f);
    if (base + 2 < NN) g_dinv[base + 2] = rsqrtf((float)v2 + 1.0f);
    if (base + 3 < NN) g_dinv[base + 3] = rsqrtf((float)v3 + 1.0f);

    int sum = v0 + v1 + v2 + v3;
    s[t] = sum;
    __syncthreads();
    for (int off = 1; off < 256; off <<= 1) {
        int add = (t >= off) ? s[t - off] : 0;
        __syncthreads();
        s[t] += add;
        __syncthreads();
    }
    int excl = s[t] - sum;          // exclusive within chunk

    if (t == 255) atomicExch(&g_pub[b], s[255] + 1);   // publish aggregate+1

    int pre = 0;                    // thread t (< b) polls predecessor t
    if (t < b) {
        int p;
        do { p = atomicAdd(&g_pub[t], 0); } while (p == 0);
        pre = p - 1;
    }
    s2[t] = pre;
    __syncthreads();
    for (int off = 128; off >= 1; off >>= 1) {
        if (t < off) s2[t] += s2[t + off];
        __syncthreads();
    }
    int P = s2[0];                  // exclusive prefix of this chunk

    int rs0 = P + excl;
    int rs1 = rs0 + v0;
    int rs2 = rs1 + v1;
    int rs3 = rs2 + v2;
    if (base + 0 < NN) { g_rowstart[base + 0] = rs0; g_cursor[base + 0] = rs0; }
    if (base + 1 < NN) { g_rowstart[base + 1] = rs1; g_cursor[base + 1] = rs1; }
    if (base + 2 < NN) { g_rowstart[base + 2] = rs2; g_cursor[base + 2] = rs2; }
    if (base + 3 < NN) { g_rowstart[base + 3] = rs3; g_cursor[base + 3] = rs3; }
}

// ---------------------------------------------------------------- CSR fill: packed (src, weight)
__global__ void k_fill(const int* __restrict__ ei32) {
    int e = blockIdx.x * blockDim.x + threadIdx.x;
    if (e < NE) {
        int r, c;
        if (g_is64) { r = ei32[2 * e]; c = ei32[2 * (NE + e)]; }
        else        { r = ei32[e];     c = ei32[NE + e]; }
        if ((unsigned)r < NN && (unsigned)c < NN) {
            int pos = atomicAdd(&g_cursor[c], 1);
            float w = g_dinv[r] * g_dinv[c];
            g_sw[pos] = make_int2(r, __float_as_int(w));
        }
    }
}

// ---------------------------------------------------------------- GEMM: g_A = x W^T  (packed f32x2)
// 128 nodes x 64 oc per block, 256 threads, each thread 4n x 8oc as 16 f32x2 acc.
// W operands come directly from LDS.128 register pairs (ulonglong2) — no packs.
__global__ void __launch_bounds__(256) k_gemm(const float* __restrict__ x,
                                              const float* __restrict__ W) {
    __shared__ float Ws[IC][OC + 4];    // [96][68]; ocg*8 offsets stay 16B-aligned
    __shared__ float xs[GN][IC + 4];    // [128][100]
    int tid = threadIdx.x;
    int b0  = blockIdx.x * GN;

    for (int i = tid; i < OC * IC; i += 256) {      // W[oc][k] -> Ws[k][oc]
        int oc = i / IC, k = i % IC;
        Ws[k][oc] = W[i];
    }
    for (int i = tid; i < GN * (IC / 4); i += 256) {   // x tile, float4 loads
        int n = i / (IC / 4), q = i % (IC / 4);
        int gn = b0 + n;
        float4 v = (gn < NN) ? ((const float4*)x)[(size_t)gn * (IC / 4) + q]
                             : make_float4(0.f, 0.f, 0.f, 0.f);
        *(float4*)&xs[n][q * 4] = v;
    }
    __syncthreads();

    int ocg = (tid & 7) * 8;       // 8 oc per thread
    int n0  = (tid >> 3) * 4;      // 4 nodes per thread
    unsigned long long acc[4][4] = {};   // [node][oc-pair]

    #pragma unroll 4
    for (int k = 0; k < IC; k++) {
        ulonglong2 wa = *(const ulonglong2*)&Ws[k][ocg];      // oc pairs 0,1
        ulonglong2 wb = *(const ulonglong2*)&Ws[k][ocg + 4];  // oc pairs 2,3
        #pragma unroll
        for (int i = 0; i < 4; i++) {
            unsigned long long xv = pack2(xs[n0 + i][k]);
            fma2(acc[i][0], xv, wa.x);
            fma2(acc[i][1], xv, wa.y);
            fma2(acc[i][2], xv, wb.x);
            fma2(acc[i][3], xv, wb.y);
        }
    }

    #pragma unroll
    for (int i = 0; i < 4; i++) {
        int gn = b0 + n0 + i;
        if (gn < NN) {
            ulonglong2* dst = (ulonglong2*)&g_A[(size_t)gn * OC + ocg];
            dst[0] = make_ulonglong2(acc[i][0], acc[i][1]);
            dst[1] = make_ulonglong2(acc[i][2], acc[i][3]);
        }
    }
}

// ---------------------------------------------------------------- gather hops
// 2 nodes per warp (half-warp of 16 lanes x float4 = full 256B row per node).
// Unroll-4: 4 edge chains in flight per node => MLP ~8 per warp.
// D[d] = dinv[d]^2 * S[d] + sum_{e: col=d} w_e * S[src_e]
// HOP2=false: S=g_A, D=g_B. HOP2=true: S=g_B, D=out with bias+sigmoid.
template <bool HOP2>
__global__ void k_gather(float* __restrict__ out, const float* __restrict__ bias) {
    int warp = (blockIdx.x * blockDim.x + threadIdx.x) >> 5;
    int node = (warp << 1) | ((threadIdx.x >> 4) & 1);
    if (node >= NN) return;
    int l = threadIdx.x & 15;

    const float4* __restrict__ Sp = (const float4*)(HOP2 ? g_B : g_A);
    float dd = g_dinv[node]; dd *= dd;
    float4 a = Sp[(size_t)node * 16 + l];
    float ax = a.x * dd, ay = a.y * dd, az = a.z * dd, aw = a.w * dd;

    int st  = g_rowstart[node];
    int cnt = g_cnt[node];
    int j = 0;
    for (; j + 4 <= cnt; j += 4) {
        int2 e0 = g_sw[st + j];
        int2 e1 = g_sw[st + j + 1];
        int2 e2 = g_sw[st + j + 2];
        int2 e3 = g_sw[st + j + 3];
        float4 v0 = Sp[(size_t)e0.x * 16 + l];
        float4 v1 = Sp[(size_t)e1.x * 16 + l];
        float4 v2 = Sp[(size_t)e2.x * 16 + l];
        float4 v3 = Sp[(size_t)e3.x * 16 + l];
        float w0 = __int_as_float(e0.y), w1 = __int_as_float(e1.y);
        float w2 = __int_as_float(e2.y), w3 = __int_as_float(e3.y);
        ax += w0 * v0.x + w1 * v1.x + w2 * v2.x + w3 * v3.x;
        ay += w0 * v0.y + w1 * v1.y + w2 * v2.y + w3 * v3.y;
        az += w0 * v0.z + w1 * v1.z + w2 * v2.z + w3 * v3.z;
        aw += w0 * v0.w + w1 * v1.w + w2 * v2.w + w3 * v3.w;
    }
    for (; j < cnt; j++) {
        int2 e0 = g_sw[st + j];
        float4 v0 = Sp[(size_t)e0.x * 16 + l];
        float w0 = __int_as_float(e0.y);
        ax += w0 * v0.x; ay += w0 * v0.y; az += w0 * v0.z; aw += w0 * v0.w;
    }

    if (HOP2) {
        float4 b = ((const float4*)bias)[l];
        ax = 1.0f / (1.0f + __expf(-(ax + b.x)));
        ay = 1.0f / (1.0f + __expf(-(ay + b.y)));
        az = 1.0f / (1.0f + __expf(-(az + b.z)));
        aw = 1.0f / (1.0f + __expf(-(aw + b.w)));
        ((float4*)out)[(size_t)node * 16 + l] = make_float4(ax, ay, az, aw);
    } else {
        ((float4*)g_B)[(size_t)node * 16 + l] = make_float4(ax, ay, az, aw);
    }
}

// ---------------------------------------------------------------- launch (7 kernels)
extern "C" void kernel_launch(void* const* d_in, const int* in_sizes, int n_in,
                              void* d_out, int out_size) {
    const float* x    = (const float*)d_in[0];
    const int*   ei32 = (const int*)d_in[1];   // raw words; dtype detected in k_init
    const float* W    = (const float*)d_in[2];
    const float* b    = (const float*)d_in[3];
    float*       out  = (float*)d_out;

    k_init <<<(NN + 255) / 256, 256>>>(ei32);
    k_count<<<(NE + 255) / 256, 256>>>(ei32);
    k_scan <<<NB, 256>>>();
    k_fill <<<(NE + 255) / 256, 256>>>(ei32);

    k_gemm <<<(NN + GN - 1) / GN, 256>>>(x, W);

    // hop 1: g_B = P * g_A          (2 nodes per warp)
    k_gather<false><<<(NN / 2 * 32 + 255) / 256, 256>>>(nullptr, nullptr);
    // hop 2 + bias + sigmoid
    k_gather<true> <<<(NN / 2 * 32 + 255) / 256, 256>>>(out, b);
}

// round 15
// speedup vs baseline: 1.2130x; 1.2130x over previous
#include <cuda_runtime.h>

#define NN 100000
#define NE 800000
#define IC 96
#define OC 64
#define GN 64             // nodes per GEMM block
#define CHUNK 1024        // scan chunk
#define NB ((NN + CHUNK - 1) / CHUNK)   // 98
static_assert(NB <= 128, "lookback scan assumes <=128 chunks");

// ---- scratch (static device globals; no allocation allowed) ----
// Referenced only from device code; never passed as kernel arguments.
__device__ int   g_is64;          // 1 if edge_index is int64, else int32
__device__ float g_dinv[NN];
__device__ int   g_cnt[NN];
__device__ int   g_rowstart[NN];
__device__ int   g_cursor[NN];
__device__ int   g_pub[128];      // lookback: chunk aggregate + 1 (0 = not ready)
__device__ __align__(16) int2  g_sw[NE];       // CSR-by-dest: (src, weight-bits)
__device__ __align__(16) float g_A[NN * OC];   // h = x W^T, hop-1 source
__device__ __align__(16) float g_B[NN * OC];   // hop-1 result / hop-2 source

// ---------------------------------------------------------------- init: zero state + dtype detect
__global__ void k_init(const int* __restrict__ ei32) {
    int i = blockIdx.x * blockDim.x + threadIdx.x;
    if (i < NN) g_cnt[i] = 0;
    if (i < 128) g_pub[i] = 0;
    if (i == 0) {
        int nz = 0;
        #pragma unroll 8
        for (int k = 0; k < 64; k++) nz |= ei32[2 * k + 1];
        g_is64 = (nz == 0) ? 1 : 0;   // odd int32 words all zero => int64 data
    }
}

// ---------------------------------------------------------------- count in-degree (c only)
__global__ void k_count(const int* __restrict__ ei32) {
    int e = blockIdx.x * blockDim.x + threadIdx.x;
    if (e < NE) {
        int c = g_is64 ? ei32[2 * (NE + e)] : ei32[NE + e];
        if ((unsigned)c < NN) atomicAdd(&g_cnt[c], 1);
    }
}

// ---------------------------------------------------------------- single-pass scan (decoupled lookback)
// Per chunk of 1024 nodes: local scan + dinv, publish aggregate, sum
// predecessor aggregates, write rowstart + cursor. 98 blocks, all co-resident.
__global__ void __launch_bounds__(256) k_scan() {
    __shared__ int s[256];
    __shared__ int s2[256];
    int t = threadIdx.x, b = blockIdx.x;
    int base = b * CHUNK + t * 4;

    int v0 = (base + 0 < NN) ? g_cnt[base + 0] : 0;
    int v1 = (base + 1 < NN) ? g_cnt[base + 1] : 0;
    int v2 = (base + 2 < NN) ? g_cnt[base + 2] : 0;
    int v3 = (base + 3 < NN) ? g_cnt[base + 3] : 0;
    // dinv while cnt is hot (deg includes +1 self loop)
    if (base + 0 < NN) g_dinv[base + 0] = rsqrtf((float)v0 + 1.0f);
    if (base + 1 < NN) g_dinv[base + 1] = rsqrtf((float)v1 + 1.0f);
    if (base + 2 < NN) g_dinv[base + 2] = rsqrtf((float)v2 + 1.0f);
    if (base + 3 < NN) g_dinv[base + 3] = rsqrtf((float)v3 + 1.0f);

    int sum = v0 + v1 + v2 + v3;
    s[t] = sum;
    __syncthreads();
    for (int off = 1; off < 256; off <<= 1) {
        int add = (t >= off) ? s[t - off] : 0;
        __syncthreads();
        s[t] += add;
        __syncthreads();
    }
    int excl = s[t] - sum;          // exclusive within chunk

    if (t == 255) atomicExch(&g_pub[b], s[255] + 1);   // publish aggregate+1

    int pre = 0;                    // thread t (< b) polls predecessor t
    if (t < b) {
        int p;
        do { p = atomicAdd(&g_pub[t], 0); } while (p == 0);
        pre = p - 1;
    }
    s2[t] = pre;
    __syncthreads();
    for (int off = 128; off >= 1; off >>= 1) {
        if (t < off) s2[t] += s2[t + off];
        __syncthreads();
    }
    int P = s2[0];                  // exclusive prefix of this chunk

    int rs0 = P + excl;
    int rs1 = rs0 + v0;
    int rs2 = rs1 + v1;
    int rs3 = rs2 + v2;
    if (base + 0 < NN) { g_rowstart[base + 0] = rs0; g_cursor[base + 0] = rs0; }
    if (base + 1 < NN) { g_rowstart[base + 1] = rs1; g_cursor[base + 1] = rs1; }
    if (base + 2 < NN) { g_rowstart[base + 2] = rs2; g_cursor[base + 2] = rs2; }
    if (base + 3 < NN) { g_rowstart[base + 3] = rs3; g_cursor[base + 3] = rs3; }
}

// ---------------------------------------------------------------- CSR fill: packed (src, weight)
__global__ void k_fill(const int* __restrict__ ei32) {
    int e = blockIdx.x * blockDim.x + threadIdx.x;
    if (e < NE) {
        int r, c;
        if (g_is64) { r = ei32[2 * e]; c = ei32[2 * (NE + e)]; }
        else        { r = ei32[e];     c = ei32[NE + e]; }
        if ((unsigned)r < NN && (unsigned)c < NN) {
            int pos = atomicAdd(&g_cursor[c], 1);
            float w = g_dinv[r] * g_dinv[c];
            g_sw[pos] = make_int2(r, __float_as_int(w));
        }
    }
}

// ---------------------------------------------------------------- GEMM: g_A = x W^T  (scalar, LDS-light)
// 64 nodes x 64 oc per block, 256 threads, 4n x 4oc per thread.
// k processed in steps of 4: x rows arrive as LDS.128 (4 per 4-k) instead of
// 16 scalar broadcasts => 8 LDS.128 + 64 FFMA per 4-k (was ~20 LDS slots).
__global__ void __launch_bounds__(256) k_gemm(const float* __restrict__ x,
                                              const float* __restrict__ W) {
    __shared__ float Ws[IC][OC + 4];    // [96][68] padded (ocq*4 stays 16B-aligned)
    __shared__ float xs[GN][IC + 4];    // [64][100]; row stride 400B (16B-aligned)
    int tid = threadIdx.x;
    int b0  = blockIdx.x * GN;

    for (int i = tid; i < OC * IC; i += 256) {      // W[oc][k] -> Ws[k][oc]
        int oc = i / IC, k = i % IC;
        Ws[k][oc] = W[i];
    }
    for (int i = tid; i < GN * (IC / 4); i += 256) {   // x tile, float4 loads
        int n = i / (IC / 4), q = i % (IC / 4);
        int gn = b0 + n;
        float4 v = (gn < NN) ? ((const float4*)x)[(size_t)gn * (IC / 4) + q]
                             : make_float4(0.f, 0.f, 0.f, 0.f);
        *(float4*)&xs[n][q * 4] = v;
    }
    __syncthreads();

    int ocq = (tid & 15) * 4;      // oc quad base
    int n0  = (tid >> 4) * 4;      // node quad base
    float acc[4][4] = {};

    #pragma unroll
    for (int k = 0; k < IC; k += 4) {
        float4 xv0 = *(const float4*)&xs[n0 + 0][k];
        float4 xv1 = *(const float4*)&xs[n0 + 1][k];
        float4 xv2 = *(const float4*)&xs[n0 + 2][k];
        float4 xv3 = *(const float4*)&xs[n0 + 3][k];
        #pragma unroll
        for (int kk = 0; kk < 4; kk++) {
            float4 w = *(const float4*)&Ws[k + kk][ocq];
            float e0 = (&xv0.x)[kk], e1 = (&xv1.x)[kk];
            float e2 = (&xv2.x)[kk], e3 = (&xv3.x)[kk];
            acc[0][0] += e0 * w.x; acc[0][1] += e0 * w.y; acc[0][2] += e0 * w.z; acc[0][3] += e0 * w.w;
            acc[1][0] += e1 * w.x; acc[1][1] += e1 * w.y; acc[1][2] += e1 * w.z; acc[1][3] += e1 * w.w;
            acc[2][0] += e2 * w.x; acc[2][1] += e2 * w.y; acc[2][2] += e2 * w.z; acc[2][3] += e2 * w.w;
            acc[3][0] += e3 * w.x; acc[3][1] += e3 * w.y; acc[3][2] += e3 * w.z; acc[3][3] += e3 * w.w;
        }
    }

    #pragma unroll
    for (int i = 0; i < 4; i++) {
        int gn = b0 + n0 + i;
        if (gn < NN)
            *(float4*)&g_A[(size_t)gn * OC + ocq] =
                make_float4(acc[i][0], acc[i][1], acc[i][2], acc[i][3]);
    }
}

// ---------------------------------------------------------------- gather hops (unchanged from 138us run)
// 2 nodes per warp (half-warp of 16 lanes x float4 = full 256B row per node).
// Unroll-4: 4 edge chains in flight per node => MLP ~8 per warp.
// D[d] = dinv[d]^2 * S[d] + sum_{e: col=d} w_e * S[src_e]
// HOP2=false: S=g_A, D=g_B. HOP2=true: S=g_B, D=out with bias+sigmoid.
template <bool HOP2>
__global__ void k_gather(float* __restrict__ out, const float* __restrict__ bias) {
    int warp = (blockIdx.x * blockDim.x + threadIdx.x) >> 5;
    int node = (warp << 1) | ((threadIdx.x >> 4) & 1);
    if (node >= NN) return;
    int l = threadIdx.x & 15;

    const float4* __restrict__ Sp = (const float4*)(HOP2 ? g_B : g_A);
    float dd = g_dinv[node]; dd *= dd;
    float4 a = Sp[(size_t)node * 16 + l];
    float ax = a.x * dd, ay = a.y * dd, az = a.z * dd, aw = a.w * dd;

    int st  = g_rowstart[node];
    int cnt = g_cnt[node];
    int j = 0;
    for (; j + 4 <= cnt; j += 4) {
        int2 e0 = g_sw[st + j];
        int2 e1 = g_sw[st + j + 1];
        int2 e2 = g_sw[st + j + 2];
        int2 e3 = g_sw[st + j + 3];
        float4 v0 = Sp[(size_t)e0.x * 16 + l];
        float4 v1 = Sp[(size_t)e1.x * 16 + l];
        float4 v2 = Sp[(size_t)e2.x * 16 + l];
        float4 v3 = Sp[(size_t)e3.x * 16 + l];
        float w0 = __int_as_float(e0.y), w1 = __int_as_float(e1.y);
        float w2 = __int_as_float(e2.y), w3 = __int_as_float(e3.y);
        ax += w0 * v0.x + w1 * v1.x + w2 * v2.x + w3 * v3.x;
        ay += w0 * v0.y + w1 * v1.y + w2 * v2.y + w3 * v3.y;
        az += w0 * v0.z + w1 * v1.z + w2 * v2.z + w3 * v3.z;
        aw += w0 * v0.w + w1 * v1.w + w2 * v2.w + w3 * v3.w;
    }
    for (; j < cnt; j++) {
        int2 e0 = g_sw[st + j];
        float4 v0 = Sp[(size_t)e0.x * 16 + l];
        float w0 = __int_as_float(e0.y);
        ax += w0 * v0.x; ay += w0 * v0.y; az += w0 * v0.z; aw += w0 * v0.w;
    }

    if (HOP2) {
        float4 b = ((const float4*)bias)[l];
        ax = 1.0f / (1.0f + __expf(-(ax + b.x)));
        ay = 1.0f / (1.0f + __expf(-(ay + b.y)));
        az = 1.0f / (1.0f + __expf(-(az + b.z)));
        aw = 1.0f / (1.0f + __expf(-(aw + b.w)));
        ((float4*)out)[(size_t)node * 16 + l] = make_float4(ax, ay, az, aw);
    } else {
        ((float4*)g_B)[(size_t)node * 16 + l] = make_float4(ax, ay, az, aw);
    }
}

// ---------------------------------------------------------------- launch (7 kernels)
extern "C" void kernel_launch(void* const* d_in, const int* in_sizes, int n_in,
                              void* d_out, int out_size) {
    const float* x    = (const float*)d_in[0];
    const int*   ei32 = (const int*)d_in[1];   // raw words; dtype detected in k_init
    const float* W    = (const float*)d_in[2];
    const float* b    = (const float*)d_in[3];
    float*       out  = (float*)d_out;

    k_init <<<(NN + 255) / 256, 256>>>(ei32);
    k_count<<<(NE + 255) / 256, 256>>>(ei32);
    k_scan <<<NB, 256>>>();
    k_fill <<<(NE + 255) / 256, 256>>>(ei32);

    k_gemm <<<(NN + GN - 1) / GN, 256>>>(x, W);

    // hop 1: g_B = P * g_A          (2 nodes per warp)
    k_gather<false><<<(NN / 2 * 32 + 255) / 256, 256>>>(nullptr, nullptr);
    // hop 2 + bias + sigmoid
    k_gather<true> <<<(NN / 2 * 32 + 255) / 256, 256>>>(out, b);
}

// round 16
// speedup vs baseline: 1.4304x; 1.1792x over previous
#include <cuda_runtime.h>

#define NN 100000
#define NE 800000
#define IC 96
#define OC 64
#define GN 64             // nodes per GEMM block
#define CHUNK 1024        // scan chunk
#define NB ((NN + CHUNK - 1) / CHUNK)   // 98
static_assert(NB <= 128, "lookback scan assumes <=128 chunks");
static_assert((NE % 4) == 0, "vector edge loads assume NE % 4 == 0");

// ---- scratch (static device globals; no allocation allowed) ----
// Referenced only from device code; never passed as kernel arguments.
__device__ int   g_is64;          // 1 if edge_index is int64, else int32
__device__ float g_dinv[NN];
__device__ int   g_cnt[NN];
__device__ int   g_rowstart[NN];
__device__ int   g_cursor[NN];
__device__ int   g_pub[128];      // lookback: chunk aggregate + 1 (0 = not ready)
__device__ __align__(16) int2  g_sw[NE];       // CSR-by-dest: (src, weight-bits)
__device__ __align__(16) float g_A[NN * OC];   // h = x W^T, hop-1 source
__device__ __align__(16) float g_B[NN * OC];   // hop-1 result / hop-2 source

// ---------------------------------------------------------------- tf32 helper
__device__ __forceinline__ unsigned tf32_of(float f) {
    unsigned r;
    asm("cvt.rna.tf32.f32 %0, %1;" : "=r"(r) : "f"(f));
    return r;
}

// ---------------------------------------------------------------- init: zero state + dtype detect
__global__ void k_init(const int* __restrict__ ei32) {
    int i = blockIdx.x * blockDim.x + threadIdx.x;
    if (i < NN) g_cnt[i] = 0;
    if (i < 128) g_pub[i] = 0;
    if (i == 0) {
        int nz = 0;
        #pragma unroll 8
        for (int k = 0; k < 64; k++) nz |= ei32[2 * k + 1];
        g_is64 = (nz == 0) ? 1 : 0;   // odd int32 words all zero => int64 data
    }
}

// ---------------------------------------------------------------- count in-degree (c only, ILP-4)
__global__ void k_count(const int* __restrict__ ei32) {
    int e = (blockIdx.x * blockDim.x + threadIdx.x) * 4;
    if (e < NE) {
        int c0, c1, c2, c3;
        if (g_is64) {
            int4 u = *(const int4*)&ei32[2 * (NE + e)];
            int4 v = *(const int4*)&ei32[2 * (NE + e) + 4];
            c0 = u.x; c1 = u.z; c2 = v.x; c3 = v.z;
        } else {
            int4 u = *(const int4*)&ei32[NE + e];
            c0 = u.x; c1 = u.y; c2 = u.z; c3 = u.w;
        }
        if ((unsigned)c0 < NN) atomicAdd(&g_cnt[c0], 1);
        if ((unsigned)c1 < NN) atomicAdd(&g_cnt[c1], 1);
        if ((unsigned)c2 < NN) atomicAdd(&g_cnt[c2], 1);
        if ((unsigned)c3 < NN) atomicAdd(&g_cnt[c3], 1);
    }
}

// ---------------------------------------------------------------- single-pass scan (decoupled lookback)
__global__ void __launch_bounds__(256) k_scan() {
    __shared__ int s[256];
    __shared__ int s2[256];
    int t = threadIdx.x, b = blockIdx.x;
    int base = b * CHUNK + t * 4;

    int v0 = (base + 0 < NN) ? g_cnt[base + 0] : 0;
    int v1 = (base + 1 < NN) ? g_cnt[base + 1] : 0;
    int v2 = (base + 2 < NN) ? g_cnt[base + 2] : 0;
    int v3 = (base + 3 < NN) ? g_cnt[base + 3] : 0;
    if (base + 0 < NN) g_dinv[base + 0] = rsqrtf((float)v0 + 1.0f);
    if (base + 1 < NN) g_dinv[base + 1] = rsqrtf((float)v1 + 1.0f);
    if (base + 2 < NN) g_dinv[base + 2] = rsqrtf((float)v2 + 1.0f);
    if (base + 3 < NN) g_dinv[base + 3] = rsqrtf((float)v3 + 1.0f);

    int sum = v0 + v1 + v2 + v3;
    s[t] = sum;
    __syncthreads();
    for (int off = 1; off < 256; off <<= 1) {
        int add = (t >= off) ? s[t - off] : 0;
        __syncthreads();
        s[t] += add;
        __syncthreads();
    }
    int excl = s[t] - sum;

    if (t == 255) atomicExch(&g_pub[b], s[255] + 1);

    int pre = 0;
    if (t < b) {
        int p;
        do { p = atomicAdd(&g_pub[t], 0); } while (p == 0);
        pre = p - 1;
    }
    s2[t] = pre;
    __syncthreads();
    for (int off = 128; off >= 1; off >>= 1) {
        if (t < off) s2[t] += s2[t + off];
        __syncthreads();
    }
    int P = s2[0];

    int rs0 = P + excl;
    int rs1 = rs0 + v0;
    int rs2 = rs1 + v1;
    int rs3 = rs2 + v2;
    if (base + 0 < NN) { g_rowstart[base + 0] = rs0; g_cursor[base + 0] = rs0; }
    if (base + 1 < NN) { g_rowstart[base + 1] = rs1; g_cursor[base + 1] = rs1; }
    if (base + 2 < NN) { g_rowstart[base + 2] = rs2; g_cursor[base + 2] = rs2; }
    if (base + 3 < NN) { g_rowstart[base + 3] = rs3; g_cursor[base + 3] = rs3; }
}

// ---------------------------------------------------------------- CSR fill (ILP-2, vector edge loads)
__global__ void k_fill(const int* __restrict__ ei32) {
    int e = (blockIdx.x * blockDim.x + threadIdx.x) * 2;
    if (e < NE) {
        int r0, c0, r1, c1;
        if (g_is64) {
            int4 rr = *(const int4*)&ei32[2 * e];
            int4 cc = *(const int4*)&ei32[2 * (NE + e)];
            r0 = rr.x; r1 = rr.z; c0 = cc.x; c1 = cc.z;
        } else {
            int2 rr = *(const int2*)&ei32[e];
            int2 cc = *(const int2*)&ei32[NE + e];
            r0 = rr.x; r1 = rr.y; c0 = cc.x; c1 = cc.y;
        }
        if ((unsigned)r0 < NN && (unsigned)c0 < NN) {
            int pos = atomicAdd(&g_cursor[c0], 1);
            g_sw[pos] = make_int2(r0, __float_as_int(g_dinv[r0] * g_dinv[c0]));
        }
        if ((unsigned)r1 < NN && (unsigned)c1 < NN) {
            int pos = atomicAdd(&g_cursor[c1], 1);
            g_sw[pos] = make_int2(r1, __float_as_int(g_dinv[r1] * g_dinv[c1]));
        }
    }
}

// ---------------------------------------------------------------- GEMM: g_A = x W^T  (tf32 tensor core)
// 64 nodes x 64 oc per block, 8 warps. Warp w: m-group (w>>1)*16, n-half (w&1)*32,
// 4 n8-subtiles, 12 k-steps of mma.m16n8k8. Tiles pre-converted to tf32 in smem.
__global__ void __launch_bounds__(256) k_gemm(const float* __restrict__ x,
                                              const float* __restrict__ W) {
    __shared__ unsigned xs[GN][IC + 4];   // tf32 bits, padded
    __shared__ unsigned Ws[OC][IC + 4];   // raw W layout [oc][k], tf32 bits
    int tid = threadIdx.x;
    int b0  = blockIdx.x * GN;

    for (int i = tid; i < OC * (IC / 4); i += 256) {   // W tile + convert
        int n = i / (IC / 4), q = i % (IC / 4);
        float4 v = ((const float4*)W)[i];
        uint4 tv = make_uint4(tf32_of(v.x), tf32_of(v.y), tf32_of(v.z), tf32_of(v.w));
        *(uint4*)&Ws[n][q * 4] = tv;
    }
    for (int i = tid; i < GN * (IC / 4); i += 256) {   // x tile + convert
        int n = i / (IC / 4), q = i % (IC / 4);
        int gn = b0 + n;
        float4 v = (gn < NN) ? ((const float4*)x)[(size_t)gn * (IC / 4) + q]
                             : make_float4(0.f, 0.f, 0.f, 0.f);
        uint4 tv = make_uint4(tf32_of(v.x), tf32_of(v.y), tf32_of(v.z), tf32_of(v.w));
        *(uint4*)&xs[n][q * 4] = tv;
    }
    __syncthreads();

    int lane = tid & 31, wrp = tid >> 5;
    int mg  = (wrp >> 1) * 16;       // m-group base row
    int ng  = (wrp & 1) * 32;        // n base
    int g4  = lane >> 2, tig = lane & 3;

    float c[4][4] = {};              // [n-subtile][c0..c3]

    #pragma unroll
    for (int k0 = 0; k0 < IC; k0 += 8) {
        unsigned a0 = xs[mg + g4][k0 + tig];
        unsigned a1 = xs[mg + g4 + 8][k0 + tig];
        unsigned a2 = xs[mg + g4][k0 + tig + 4];
        unsigned a3 = xs[mg + g4 + 8][k0 + tig + 4];
        #pragma unroll
        for (int nt = 0; nt < 4; nt++) {
            int n = ng + nt * 8 + g4;
            unsigned b0r = Ws[n][k0 + tig];
            unsigned b1r = Ws[n][k0 + tig + 4];
            asm("mma.sync.aligned.m16n8k8.row.col.f32.tf32.tf32.f32 "
                "{%0,%1,%2,%3}, {%4,%5,%6,%7}, {%8,%9}, {%0,%1,%2,%3};"
                : "+f"(c[nt][0]), "+f"(c[nt][1]), "+f"(c[nt][2]), "+f"(c[nt][3])
                : "r"(a0), "r"(a1), "r"(a2), "r"(a3), "r"(b0r), "r"(b1r));
        }
    }

    int row0 = b0 + mg + g4;
    int row1 = row0 + 8;
    #pragma unroll
    for (int nt = 0; nt < 4; nt++) {
        int col = ng + nt * 8 + tig * 2;
        if (row0 < NN) *(float2*)&g_A[(size_t)row0 * OC + col] = make_float2(c[nt][0], c[nt][1]);
        if (row1 < NN) *(float2*)&g_A[(size_t)row1 * OC + col] = make_float2(c[nt][2], c[nt][3]);
    }
}

// ---------------------------------------------------------------- gather hops (unchanged)
// 2 nodes per warp (half-warp of 16 lanes x float4 = full 256B row per node).
// Unroll-4: 4 edge chains in flight per node => MLP ~8 per warp.
template <bool HOP2>
__global__ void k_gather(float* __restrict__ out, const float* __restrict__ bias) {
    int warp = (blockIdx.x * blockDim.x + threadIdx.x) >> 5;
    int node = (warp << 1) | ((threadIdx.x >> 4) & 1);
    if (node >= NN) return;
    int l = threadIdx.x & 15;

    const float4* __restrict__ Sp = (const float4*)(HOP2 ? g_B : g_A);
    float dd = g_dinv[node]; dd *= dd;
    float4 a = Sp[(size_t)node * 16 + l];
    float ax = a.x * dd, ay = a.y * dd, az = a.z * dd, aw = a.w * dd;

    int st  = g_rowstart[node];
    int cnt = g_cnt[node];
    int j = 0;
    for (; j + 4 <= cnt; j += 4) {
        int2 e0 = g_sw[st + j];
        int2 e1 = g_sw[st + j + 1];
        int2 e2 = g_sw[st + j + 2];
        int2 e3 = g_sw[st + j + 3];
        float4 v0 = Sp[(size_t)e0.x * 16 + l];
        float4 v1 = Sp[(size_t)e1.x * 16 + l];
        float4 v2 = Sp[(size_t)e2.x * 16 + l];
        float4 v3 = Sp[(size_t)e3.x * 16 + l];
        float w0 = __int_as_float(e0.y), w1 = __int_as_float(e1.y);
        float w2 = __int_as_float(e2.y), w3 = __int_as_float(e3.y);
        ax += w0 * v0.x + w1 * v1.x + w2 * v2.x + w3 * v3.x;
        ay += w0 * v0.y + w1 * v1.y + w2 * v2.y + w3 * v3.y;
        az += w0 * v0.z + w1 * v1.z + w2 * v2.z + w3 * v3.z;
        aw += w0 * v0.w + w1 * v1.w + w2 * v2.w + w3 * v3.w;
    }
    for (; j < cnt; j++) {
        int2 e0 = g_sw[st + j];
        float4 v0 = Sp[(size_t)e0.x * 16 + l];
        float w0 = __int_as_float(e0.y);
        ax += w0 * v0.x; ay += w0 * v0.y; az += w0 * v0.z; aw += w0 * v0.w;
    }

    if (HOP2) {
        float4 b = ((const float4*)bias)[l];
        ax = 1.0f / (1.0f + __expf(-(ax + b.x)));
        ay = 1.0f / (1.0f + __expf(-(ay + b.y)));
        az = 1.0f / (1.0f + __expf(-(az + b.z)));
        aw = 1.0f / (1.0f + __expf(-(aw + b.w)));
        ((float4*)out)[(size_t)node * 16 + l] = make_float4(ax, ay, az, aw);
    } else {
        ((float4*)g_B)[(size_t)node * 16 + l] = make_float4(ax, ay, az, aw);
    }
}

// ---------------------------------------------------------------- launch (7 kernels)
// gemm placed 4th so the ncu capture window (slot 4) lands on it next round.
extern "C" void kernel_launch(void* const* d_in, const int* in_sizes, int n_in,
                              void* d_out, int out_size) {
    const float* x    = (const float*)d_in[0];
    const int*   ei32 = (const int*)d_in[1];   // raw words; dtype detected in k_init
    const float* W    = (const float*)d_in[2];
    const float* b    = (const float*)d_in[3];
    float*       out  = (float*)d_out;

    k_init <<<(NN + 255) / 256, 256>>>(ei32);
    k_count<<<(NE / 4 + 255) / 256, 256>>>(ei32);
    k_scan <<<NB, 256>>>();
    k_gemm <<<(NN + GN - 1) / GN, 256>>>(x, W);
    k_fill <<<(NE / 2 + 255) / 256, 256>>>(ei32);

    // hop 1: g_B = P * g_A          (2 nodes per warp)
    k_gather<false><<<(NN / 2 * 32 + 255) / 256, 256>>>(nullptr, nullptr);
    // hop 2 + bias + sigmoid
    k_gather<true> <<<(NN / 2 * 32 + 255) / 256, 256>>>(out, b);
}